// round 4
// baseline (speedup 1.0000x reference)
#include <cuda_runtime.h>
#include <cstdint>

// SoftDTW-style scan: out[b,0,:] = x[b,0,:]
// out[b,t,j] = x[b,t,j] + soft(out[b,t-1,j], out[b,t-1,j-1])
//   soft(a,bb) = bb + d*sigmoid(d), d = a-bb;  global column 0 keeps 'a'.
//
// 1 CTA per batch, 512 threads, 4 adjacent columns per thread. NO per-step
// CTA barrier: warps form a software pipeline. The single cross-warp value
// per step (warp's rightmost column) goes through a per-boundary smem ring of
// (value, step-tag) 64-bit slots, accessed with single v2.u32 volatile
// ld/st (atomic 64-bit -> tag and value cannot tear). Consumer warp w at
// step t polls ring[w-1] slot (t-1)&63 for tag t-1. Back-pressure: consumers
// advertise progress; producers re-check a cached copy every ~RING steps.
// Intra-warp neighbor exchange stays in shfl. x rows register-prefetched
// (PF=3, static indices; 1023 = 3*341).

#define SEQ_T 1024
#define COLS  2048
#define NT    512
#define CPT   4
#define NWARP (NT / 32)     // 16
#define RING  64            // slots per boundary (power of 2)
#define PF    3

__device__ __forceinline__ float tanh_fast(float v)
{
    float r;
    asm("tanh.approx.f32 %0, %1;" : "=f"(r) : "f"(v));
    return r;
}

// soft(a, bb) = bb + d * sigmoid(d), d = a - bb
__device__ __forceinline__ float softstep(float a, float bb)
{
    float d = a - bb;
    float p = fmaf(0.5f, tanh_fast(0.5f * d), 0.5f);
    return fmaf(d, p, bb);
}

__device__ __forceinline__ void ring_store(uint32_t addr, float v, unsigned tag)
{
    asm volatile("st.volatile.shared.v2.u32 [%0], {%1, %2};"
                 :: "r"(addr), "r"(__float_as_uint(v)), "r"(tag) : "memory");
}

__device__ __forceinline__ uint2 ring_load(uint32_t addr)
{
    uint2 s;
    asm volatile("ld.volatile.shared.v2.u32 {%0, %1}, [%2];"
                 : "=r"(s.x), "=r"(s.y) : "r"(addr) : "memory");
    return s;
}

__global__ __launch_bounds__(NT, 1)
void softdtw_pipe_kernel(const float* __restrict__ x, float* __restrict__ out)
{
    __shared__ uint2 ring[NWARP][RING];       // (value bits, step tag)
    __shared__ volatile int cons_prog[NWARP]; // last step consumed by warp w

    const int tid  = threadIdx.x;
    const int warp = tid >> 5;
    const int lane = tid & 31;
    const int b    = blockIdx.x;

    // One-time init: invalidate all tags (smem contents are undefined).
    for (int i = tid; i < NWARP * RING; i += NT)
        ((uint2*)ring)[i] = make_uint2(0u, 0xFFFFFFFFu);
    if (lane == 0) cons_prog[warp] = 0;
    __syncthreads();   // only barrier in the kernel

    const uint32_t my_ring   = (uint32_t)__cvta_generic_to_shared(&ring[warp][0]);
    const uint32_t left_ring = (uint32_t)__cvta_generic_to_shared(&ring[(warp > 0 ? warp : 1) - 1][0]);
    const bool is_prod = (lane == 31) && (warp != NWARP - 1);
    const bool is_cons = (lane == 0)  && (warp != 0);

    const size_t base = (size_t)b * SEQ_T * COLS + (size_t)tid * CPT;
    const float* xb = x + base;
    float*       ob = out + base;

    // t = 0: carry = x row 0, emit it, publish boundary with tag 0.
    float4 cr = __ldg((const float4*)xb);
    *(float4*)ob = cr;
    float c0 = cr.x, c1 = cr.y, c2 = cr.z, c3 = cr.w;
    if (is_prod) ring_store(my_ring, c3, 0u);

    int cons_cache = 0;   // producer's cached view of right neighbor progress

    // Register prefetch of x rows 1..PF (static slot indices only).
    float4 xf[PF];
#pragma unroll
    for (int i = 0; i < PF; i++)
        xf[i] = __ldg((const float4*)(xb + (size_t)(1 + i) * COLS));

    for (int t = 1; t < SEQ_T; t += PF) {
#pragma unroll
        for (int i = 0; i < PF; i++) {
            const int tt = t + i;

            // Left value: previous thread's current c3.
            float lv = __shfl_up_sync(0xffffffffu, c3, 1);
            if (is_cons) {
                const uint32_t a = left_ring + (((tt - 1) & (RING - 1)) << 3);
                uint2 s = ring_load(a);
                if (s.y != (unsigned)(tt - 1)) {
                    do { __nanosleep(40); s = ring_load(a); }
                    while (s.y != (unsigned)(tt - 1));
                }
                lv = __uint_as_float(s.x);
                cons_prog[warp] = tt;
            }

            const float4 xv = xf[i];
            if (tt + PF < SEQ_T)
                xf[i] = __ldg((const float4*)(xb + (size_t)(tt + PF) * COLS));

            float s0 = softstep(c0, lv);
            float s1 = softstep(c1, c0);
            float s2 = softstep(c2, c1);
            float s3 = softstep(c3, c2);
            if (warp == 0 && lane == 0) s0 = c0;   // global column 0

            c0 = s0 + xv.x;
            c1 = s1 + xv.y;
            c2 = s2 + xv.z;
            c3 = s3 + xv.w;

            *(float4*)(ob + (size_t)tt * COLS) = make_float4(c0, c1, c2, c3);

            if (is_prod) {
                if (tt >= cons_cache + RING) {   // rare: refresh / back-pressure
                    do { __nanosleep(40); cons_cache = cons_prog[warp + 1]; }
                    while (tt >= cons_cache + RING);
                }
                ring_store(my_ring + ((tt & (RING - 1)) << 3), c3, (unsigned)tt);
            }
        }
    }
}

extern "C" void kernel_launch(void* const* d_in, const int* in_sizes, int n_in,
                              void* d_out, int out_size)
{
    (void)in_sizes; (void)n_in; (void)out_size;
    const float* x = (const float*)d_in[0];
    float*       o = (float*)d_out;
    softdtw_pipe_kernel<<<32, NT>>>(x, o);
}

// round 7
// speedup vs baseline: 1.8325x; 1.8325x over previous
#include <cuda_runtime.h>

// SoftDTW-style scan with warp-halo trapezoidal blocking.
//
// out[b,0,:] = x[b,0,:]
// out[b,t,j] = x[b,t,j] + soft(out[b,t-1,j], out[b,t-1,j-1])
//   soft(a,bb) = bb + d*sigmoid(d), d = a-bb;  global column 0 keeps 'a'.
//
// 1 CTA/batch, 512 threads, 4 adjacent columns per thread in registers.
// Each warp owns 128 columns plus an 8-column HALO (a register copy of the 8
// columns left of its range, one column per lane 24..31, updated in lockstep
// with the real owners). The halo lets the warp run KB=8 steps with NO
// cross-warp communication: halo column j is correct through row t0+j, and
// own column 0 at block-step i reads halo col 7 at row t0+i-1 (valid for all
// i<=8). One __syncthreads per 8 steps refreshes the halo from the left
// warp's top 8 columns via smem (parity double-buffered). Intra-warp
// neighbor values go through shfl. x is register-prefetched PF=4 rows ahead
// with compile-time slot indices (i & 3 inside the unrolled 8-step body).

#define SEQ_T 1024
#define COLS  2048
#define NT    512
#define CPT   4
#define NWARP (NT / 32)   // 16
#define KB    8           // steps per barrier-free block
#define PF    4           // prefetch depth (divides KB)

__device__ __forceinline__ float tanh_fast(float v)
{
    float r;
    asm("tanh.approx.f32 %0, %1;" : "=f"(r) : "f"(v));
    return r;
}

// soft(a, bb) = bb + d * sigmoid(d), d = a - bb
__device__ __forceinline__ float softstep(float a, float bb)
{
    float d = a - bb;
    float p = fmaf(0.5f, tanh_fast(0.5f * d), 0.5f);
    return fmaf(d, p, bb);
}

__global__ __launch_bounds__(NT, 1)
void softdtw_halo_kernel(const float* __restrict__ x, float* __restrict__ out)
{
    __shared__ float4 xch[2][NWARP][2];   // lanes 30,31 carries per warp

    const int tid  = threadIdx.x;
    const int warp = tid >> 5;
    const int lane = tid & 31;
    const int b    = blockIdx.x;

    const size_t brow = (size_t)b * SEQ_T * COLS;
    const float* xb = x   + brow + (size_t)tid * CPT;
    float*       ob = out + brow + (size_t)tid * CPT;

    // Halo column for lanes 24..31 of warp>0: column warp*128 - 8 + (lane-24).
    const bool   haloln = (warp > 0) && (lane >= 24);
    const float* hx_ptr = x + brow + warp * 128 - 8 + (lane - 24); // deref only if haloln

    // t = 0: carry = x row 0, emit it.
    float4 cr = __ldg((const float4*)xb);
    *(float4*)ob = cr;
    float c0 = cr.x, c1 = cr.y, c2 = cr.z, c3 = cr.w;
    float h  = 0.0f;

    // Register prefetch of rows 1..PF (own float4 + halo float).
    float4 xf[PF];
    float  hxf[PF];
#pragma unroll
    for (int i = 0; i < PF; i++) {
        xf[i]  = __ldg((const float4*)(xb + (size_t)(1 + i) * COLS));
        hxf[i] = haloln ? __ldg(hx_ptr + (size_t)(1 + i) * COLS) : 0.0f;
    }

    const int NBLK = (SEQ_T + KB - 1) / KB;   // 128; steps 1..1023
    for (int blk = 0; blk < NBLK; blk++) {
        const int par = blk & 1;

        // Refresh halo: publish top 8 columns (lanes 30,31), one barrier.
        if (lane >= 30) xch[par][warp][lane - 30] = make_float4(c0, c1, c2, c3);
        __syncthreads();
        if (haloln) h = ((const float*)&xch[par][warp - 1][0])[lane - 24];

#pragma unroll
        for (int i = 0; i < KB; i++) {
            const int tt = blk * KB + 1 + i;
            if (tt < SEQ_T) {                       // warp-uniform
                // Cross-lane reads of OLD (row tt-1) values.
                float lv  = __shfl_up_sync(0xffffffffu, c3, 1);
                float h31 = __shfl_sync(0xffffffffu, h, 31);
                float hl  = __shfl_up_sync(0xffffffffu, h, 1);
                if (lane == 0) lv = h31;            // own col0's left = halo col7

                const float4 xv = xf[i & (PF - 1)];
                const float  hv = hxf[i & (PF - 1)];
                if (tt + PF < SEQ_T) {
                    xf[i & (PF - 1)]  = __ldg((const float4*)(xb + (size_t)(tt + PF) * COLS));
                    hxf[i & (PF - 1)] = haloln ? __ldg(hx_ptr + (size_t)(tt + PF) * COLS) : 0.0f;
                }

                float s0 = softstep(c0, lv);
                float s1 = softstep(c1, c0);
                float s2 = softstep(c2, c1);
                float s3 = softstep(c3, c2);
                float sh = softstep(h,  hl);        // halo update (lanes 24..31)
                if (warp == 0 && lane == 0) s0 = c0; // global column 0 keeps 'a'

                c0 = s0 + xv.x;
                c1 = s1 + xv.y;
                c2 = s2 + xv.z;
                c3 = s3 + xv.w;
                h  = sh + hv;

                *(float4*)(ob + (size_t)tt * COLS) = make_float4(c0, c1, c2, c3);
            }
        }
    }
}

extern "C" void kernel_launch(void* const* d_in, const int* in_sizes, int n_in,
                              void* d_out, int out_size)
{
    (void)in_sizes; (void)n_in; (void)out_size;
    const float* x = (const float*)d_in[0];
    float*       o = (float*)d_out;
    softdtw_halo_kernel<<<32, NT>>>(x, o);
}

// round 9
// speedup vs baseline: 4.0306x; 2.1996x over previous
#include <cuda_runtime.h>
#include <cstdint>

// SoftDTW-style scan: warp-halo trapezoid + cp.async double-buffered x staging.
//
// out[b,0,:] = x[b,0,:]
// out[b,t,j] = x[b,t,j] + soft(out[b,t-1,j], out[b,t-1,j-1])
//   soft(a,bb) = bb + d*sigmoid(d), d = a-bb;  global column 0 keeps 'a'.
//
// 1 CTA/batch, 512 threads, 4 adjacent columns/thread in registers. Each warp
// owns 128 columns + an 8-column register halo (lanes 24..31), letting it run
// KB=8 steps with no cross-warp talk; one __syncthreads per block refreshes
// the halo via smem. x rows are staged through a 2-deep smem ring filled by
// cp.async one full block (8 steps) ahead: each thread copies exactly the
// bytes it later reads, so the x path needs no barriers — wait_group 1 per
// thread is enough. This fixes round-7's latency collapse (rolling register
// prefetch lead shrank with t_step; MLP ~5/warp, DRAM 11.8%).

#define SEQ_T 1024
#define COLS  2048
#define NT    512
#define CPT   4
#define NWARP (NT / 32)   // 16
#define KB    8
#define NBLK  ((SEQ_T + KB - 1) / KB)   // 128

#define XBUF_BYTES (2 * KB * COLS * 4)        // 131072
#define XH_BYTES   (2 * KB * NWARP * 8 * 4)   // 8192
#define XCH_OFF    (XBUF_BYTES + XH_BYTES)    // 139264
#define SMEM_TOTAL (XCH_OFF + 2 * NWARP * 2 * 16)  // +1KB

__device__ __forceinline__ float tanh_fast(float v)
{
    float r;
    asm("tanh.approx.f32 %0, %1;" : "=f"(r) : "f"(v));
    return r;
}

__device__ __forceinline__ float softstep(float a, float bb)
{
    float d = a - bb;
    float p = fmaf(0.5f, tanh_fast(0.5f * d), 0.5f);
    return fmaf(d, p, bb);
}

__device__ __forceinline__ void cp16(uint32_t dst, const float* src)
{
    asm volatile("cp.async.ca.shared.global [%0], [%1], 16;" :: "r"(dst), "l"(src));
}
__device__ __forceinline__ void cp4(uint32_t dst, const float* src)
{
    asm volatile("cp.async.ca.shared.global [%0], [%1], 4;" :: "r"(dst), "l"(src));
}
__device__ __forceinline__ void cp_commit()
{
    asm volatile("cp.async.commit_group;" ::: "memory");
}
__device__ __forceinline__ void cp_wait1()
{
    asm volatile("cp.async.wait_group 1;" ::: "memory");
}

__global__ __launch_bounds__(NT, 1)
void softdtw_cps_kernel(const float* __restrict__ x, float* __restrict__ out)
{
    extern __shared__ char smem_raw[];
    float*  xbuf = (float*)smem_raw;                       // [2][KB][COLS]
    float*  xh   = (float*)(smem_raw + XBUF_BYTES);        // [2][KB][NWARP*8]
    float4* xch  = (float4*)(smem_raw + XCH_OFF);          // [2][NWARP][2]

    const uint32_t xbuf_s = (uint32_t)__cvta_generic_to_shared(xbuf);
    const uint32_t xh_s   = (uint32_t)__cvta_generic_to_shared(xh);

    const int tid  = threadIdx.x;
    const int warp = tid >> 5;
    const int lane = tid & 31;
    const int b    = blockIdx.x;

    const size_t brow = (size_t)b * SEQ_T * COLS;
    const int    colb = tid * CPT;
    const float* xb   = x   + brow + colb;
    float*       ob   = out + brow + colb;

    const bool haloln = (warp > 0) && (lane >= 24);
    const int  hidx   = warp * 8 + (lane - 24);            // slot in xh row
    const int  hcol   = warp * 128 - 8 + (lane - 24);      // gmem column

    // t = 0: carry = x row 0, emit it.
    float4 cr = __ldg((const float4*)xb);
    *(float4*)ob = cr;
    float c0 = cr.x, c1 = cr.y, c2 = cr.z, c3 = cr.w;
    float h  = 0.0f;

    // Issue async copies for a block's 8 rows into buffer (blk & 1).
    auto issue_copy = [&](int blk) {
        const int par = blk & 1;
#pragma unroll
        for (int r = 0; r < KB; r++) {
            int t = 1 + blk * KB + r;
            if (t > SEQ_T - 1) t = SEQ_T - 1;
            const size_t rowoff = brow + (size_t)t * COLS;
            cp16(xbuf_s + (uint32_t)(((par * KB + r) * COLS + colb) * 4),
                 x + rowoff + colb);
            if (haloln)
                cp4(xh_s + (uint32_t)(((par * KB + r) * (NWARP * 8) + hidx) * 4),
                    x + rowoff + hcol);
        }
        cp_commit();
    };

    issue_copy(0);
    issue_copy(1);

    for (int blk = 0; blk < NBLK; blk++) {
        const int par = blk & 1;

        cp_wait1();   // this thread's rows for block `blk` are in smem

        // Halo refresh: publish top 8 columns (lanes 30,31), one barrier.
        if (lane >= 30) xch[par * NWARP * 2 + warp * 2 + (lane - 30)] =
                            make_float4(c0, c1, c2, c3);
        __syncthreads();
        if (haloln)
            h = ((const float*)&xch[par * NWARP * 2 + (warp - 1) * 2])[lane - 24];

#pragma unroll
        for (int i = 0; i < KB; i++) {
            const int tt = blk * KB + 1 + i;
            if (tt < SEQ_T) {                              // warp-uniform
                const float4 xv = *(const float4*)&xbuf[(par * KB + i) * COLS + colb];
                const float  hv = haloln ? xh[(par * KB + i) * (NWARP * 8) + hidx] : 0.0f;

                // One rotate serves both: lane0 gets h[31] (halo col 7);
                // halo lanes get left halo value.
                float hrot = __shfl_sync(0xffffffffu, h, (lane + 31) & 31);
                float lv   = __shfl_up_sync(0xffffffffu, c3, 1);
                if (lane == 0) lv = hrot;

                float s0 = softstep(c0, lv);
                float s1 = softstep(c1, c0);
                float s2 = softstep(c2, c1);
                float s3 = softstep(c3, c2);
                float sh = softstep(h,  hrot);
                if (warp == 0 && lane == 0) s0 = c0;       // global column 0

                c0 = s0 + xv.x;
                c1 = s1 + xv.y;
                c2 = s2 + xv.z;
                c3 = s3 + xv.w;
                h  = sh + hv;

                *(float4*)(ob + (size_t)tt * COLS) = make_float4(c0, c1, c2, c3);
            }
        }

        // Refill the buffer just consumed for block blk+2.
        if (blk + 2 < NBLK) issue_copy(blk + 2);
        else                cp_commit();   // keep group accounting uniform
    }
}

extern "C" void kernel_launch(void* const* d_in, const int* in_sizes, int n_in,
                              void* d_out, int out_size)
{
    (void)in_sizes; (void)n_in; (void)out_size;
    const float* x = (const float*)d_in[0];
    float*       o = (float*)d_out;

    cudaFuncSetAttribute(softdtw_cps_kernel,
                         cudaFuncAttributeMaxDynamicSharedMemorySize, SMEM_TOTAL);
    softdtw_cps_kernel<<<32, NT, SMEM_TOTAL>>>(x, o);
}

// round 15
// speedup vs baseline: 4.7320x; 1.1740x over previous
#include <cuda_runtime.h>
#include <cstdint>

// SoftDTW-style scan: CTA-column-split + warp-halo trapezoid + cp.async staging.
//
// out[b,0,:] = x[b,0,:]
// out[b,t,j] = x[b,t,j] + soft(out[b,t-1,j], out[b,t-1,j-1])
//   soft(a,bb) = bb + d*sigmoid(d), d = a-bb;  global column 0 keeps 'a'.
//
// 128 CTAs (32 batches x 4 column chunks), 128 threads each, 4 cols/thread.
// Each warp owns 128 columns + a 16-column register halo (lanes 16..31), so
// it runs KB=16 steps with no communication; halo refresh once per block:
//   warps 1..3: from left warp via smem (parity double-buffered, 1 barrier)
//   warp 0 (chunk k>0): from left CTA via write-once global slots
//     g_ex[b][k-1][blk][16] + flag (release: syncwarp+threadfence+flag store;
//     acquire: poll+threadfence). Acyclic left->right, all CTAs co-resident.
// x rows staged through a 2-deep cp.async smem ring one block ahead; each
// thread copies exactly what it reads -> per-thread wait_group, no barrier.

#define SEQ_T  1024
#define COLS   2048
#define NBATCH 32
#define CSPLIT 4
#define NT     128
#define NWARP  4
#define CPT    4
#define CCOLS  (NT * CPT)                   // 512
#define KB     16
#define NBLK   ((SEQ_T - 1 + KB - 1) / KB)  // 64
#define HW     16

__device__ float g_ex[NBATCH][CSPLIT][NBLK][HW];
__device__ int   g_flag[NBATCH][CSPLIT][NBLK];

#define XBUF_FLOATS (2 * KB * CCOLS)        // 16384
#define XH_FLOATS   (2 * KB * NWARP * HW)   // 2048
#define XCH_FLOATS  (2 * NWARP * HW)        // 128
#define SMEM_TOTAL  ((XBUF_FLOATS + XH_FLOATS + XCH_FLOATS) * 4)

__device__ __forceinline__ float tanh_fast(float v)
{
    float r;
    asm("tanh.approx.f32 %0, %1;" : "=f"(r) : "f"(v));
    return r;
}

__device__ __forceinline__ float softstep(float a, float bb)
{
    float d = a - bb;
    float p = fmaf(0.5f, tanh_fast(0.5f * d), 0.5f);
    return fmaf(d, p, bb);
}

__device__ __forceinline__ void cp16(uint32_t dst, const float* src)
{
    asm volatile("cp.async.ca.shared.global [%0], [%1], 16;" :: "r"(dst), "l"(src));
}
__device__ __forceinline__ void cp4(uint32_t dst, const float* src)
{
    asm volatile("cp.async.ca.shared.global [%0], [%1], 4;" :: "r"(dst), "l"(src));
}
__device__ __forceinline__ void cp_commit()
{
    asm volatile("cp.async.commit_group;" ::: "memory");
}
__device__ __forceinline__ void cp_wait1()
{
    asm volatile("cp.async.wait_group 1;" ::: "memory");
}

__global__ __launch_bounds__(NT, 1)
void softdtw_split_kernel(const float* __restrict__ x, float* __restrict__ out)
{
    extern __shared__ float sm[];
    float* xbuf = sm;                              // [2][KB][CCOLS]
    float* xh   = sm + XBUF_FLOATS;                // [2][KB][NWARP*HW]
    float* xch  = sm + XBUF_FLOATS + XH_FLOATS;    // [2][NWARP][HW]
    const uint32_t xbuf_s = (uint32_t)__cvta_generic_to_shared(xbuf);
    const uint32_t xh_s   = (uint32_t)__cvta_generic_to_shared(xh);

    const int tid  = threadIdx.x;
    const int warp = tid >> 5;
    const int lane = tid & 31;
    const int bb   = blockIdx.x >> 2;     // batch
    const int kk   = blockIdx.x & 3;      // column chunk

    const size_t brow  = (size_t)bb * SEQ_T * COLS;
    const int    cbase = kk * CCOLS;
    const int    colg  = cbase + tid * CPT;
    const float* xb    = x   + brow + colg;
    float*       ob    = out + brow + colg;

    const bool haloln = (lane >= 16) && (warp > 0 || kk > 0);
    const int  hcolg  = cbase + warp * 128 - HW + (lane - 16);  // global halo col
    const int  hslot  = warp * HW + (lane - 16);

    // t = 0: carry = x row 0, emit it.
    float4 cr = __ldg((const float4*)xb);
    *(float4*)ob = cr;
    float c0 = cr.x, c1 = cr.y, c2 = cr.z, c3 = cr.w;
    float h  = 0.0f;

    auto issue_copy = [&](int blk) {
        const int par = blk & 1;
#pragma unroll
        for (int r = 0; r < KB; r++) {
            int t = 1 + blk * KB + r;
            if (t > SEQ_T - 1) t = SEQ_T - 1;
            const float* row = x + brow + (size_t)t * COLS;
            cp16(xbuf_s + (uint32_t)(((par * KB + r) * CCOLS + tid * CPT) * 4),
                 row + colg);
            if (haloln)
                cp4(xh_s + (uint32_t)(((par * KB + r) * (NWARP * HW) + hslot) * 4),
                    row + hcolg);
        }
        cp_commit();
    };

    issue_copy(0);
    issue_copy(1);

    volatile int* lflag = (kk > 0) ? &g_flag[bb][kk - 1][0] : (volatile int*)0;

    for (int blk = 0; blk < NBLK; blk++) {
        const int par = blk & 1;

        // Cross-CTA publish: current carries (= state at this block's start).
        if (kk < CSPLIT - 1 && warp == 3) {
            if (lane >= 28)
                *(float4*)&g_ex[bb][kk][blk][(lane - 28) * 4] =
                    make_float4(c0, c1, c2, c3);
            __syncwarp();
            __threadfence();
            if (lane == 28) *((volatile int*)&g_flag[bb][kk][blk]) = 1;
        }

        cp_wait1();   // this thread's x rows for block `blk` are in smem

        // Intra-CTA publish of each warp's top 16 columns.
        if (lane >= 28)
            *(float4*)&xch[(par * NWARP + warp) * HW + (lane - 28) * 4] =
                make_float4(c0, c1, c2, c3);
        __syncthreads();

        // Halo refresh.
        if (lane >= 16) {
            if (warp > 0) {
                h = xch[(par * NWARP + warp - 1) * HW + (lane - 16)];
            } else if (kk > 0) {
                if (lane == 16) {
                    while (lflag[blk] == 0) __nanosleep(32);
                }
                __syncwarp(0xffff0000u);
                __threadfence();   // acquire: order data loads after flag
                h = g_ex[bb][kk - 1][blk][lane - 16];
            }
        }

#pragma unroll
        for (int i = 0; i < KB; i++) {
            const int tt = blk * KB + 1 + i;
            if (tt < SEQ_T) {                       // warp-uniform
                const float4 xv = *(const float4*)&xbuf[(par * KB + i) * CCOLS + tid * CPT];
                const float  hv = haloln ? xh[(par * KB + i) * (NWARP * HW) + hslot] : 0.0f;

                // One rotate serves both: lane0 gets h[31] (halo col 15);
                // halo lanes get their left halo value.
                float hrot = __shfl_sync(0xffffffffu, h, (lane + 31) & 31);
                float lv   = __shfl_up_sync(0xffffffffu, c3, 1);
                if (lane == 0) lv = hrot;

                float s0 = softstep(c0, lv);
                float s1 = softstep(c1, c0);
                float s2 = softstep(c2, c1);
                float s3 = softstep(c3, c2);
                float sh = softstep(h,  hrot);
                if (kk == 0 && warp == 0 && lane == 0) s0 = c0;  // global col 0

                c0 = s0 + xv.x;
                c1 = s1 + xv.y;
                c2 = s2 + xv.z;
                c3 = s3 + xv.w;
                h  = sh + hv;

                *(float4*)(ob + (size_t)tt * COLS) = make_float4(c0, c1, c2, c3);
            }
        }

        if (blk + 2 < NBLK) issue_copy(blk + 2);
        else                cp_commit();   // keep group accounting uniform
    }
}

extern "C" void kernel_launch(void* const* d_in, const int* in_sizes, int n_in,
                              void* d_out, int out_size)
{
    (void)in_sizes; (void)n_in; (void)out_size;
    const float* x = (const float*)d_in[0];
    float*       o = (float*)d_out;

    void* pflag = nullptr;
    cudaGetSymbolAddress(&pflag, g_flag);
    cudaMemsetAsync(pflag, 0, sizeof(int) * NBATCH * CSPLIT * NBLK);

    cudaFuncSetAttribute(softdtw_split_kernel,
                         cudaFuncAttributeMaxDynamicSharedMemorySize, SMEM_TOTAL);
    softdtw_split_kernel<<<NBATCH * CSPLIT, NT, SMEM_TOTAL>>>(x, o);
}